// round 1
// baseline (speedup 1.0000x reference)
#include <cuda_runtime.h>

#define NUP1   100001          // NUM_USERS + 1
#define NNODES 200001          // NUM_USERS + 1 + NUM_ITEMS
#define NV     (NNODES * 16)   // float4 elements per node buffer (64 floats / node)

// Ping-pong propagation buffers + accumulator (static device scratch; no allocs)
__device__ float4 g_A[NV];
__device__ float4 g_B[NV];
__device__ float4 g_acc[NV];

// Build all_emb = concat(user_emb, item_emb[1:]) into A and acc; zero B.
__global__ void init_kernel(const float4* __restrict__ user4,
                            const float4* __restrict__ item4) {
    int i = blockIdx.x * blockDim.x + threadIdx.x;
    if (i >= NV) return;
    float4 v = (i < NUP1 * 16) ? user4[i] : item4[i - NUP1 * 16 + 16];
    g_A[i]   = v;
    g_acc[i] = v;
    g_B[i]   = make_float4(0.f, 0.f, 0.f, 0.f);
}

// y[row] += val * x[col], 16 threads per edge, float4 vector atomics.
// dir=0: x=A, y=B ; dir=1: x=B, y=A
__global__ void spmm_kernel(const int*   __restrict__ rows,
                            const int*   __restrict__ cols,
                            const float* __restrict__ vals,
                            int nnz, int dir) {
    long long t = (long long)blockIdx.x * blockDim.x + threadIdx.x;
    int e = (int)(t >> 4);
    int d = (int)(t & 15);
    if (e >= nnz) return;

    const float4* __restrict__ x = dir ? g_B : g_A;
    float4*       __restrict__ y = dir ? g_A : g_B;

    float v = __ldg(&vals[e]);
    int   c = __ldg(&cols[e]);
    int   r = __ldg(&rows[e]);

    float4 xv = __ldg(&x[c * 16 + d]);
    float4 m  = make_float4(v * xv.x, v * xv.y, v * xv.z, v * xv.w);
    atomicAdd(&y[r * 16 + d], m);
}

// acc += src; zero the other buffer (it becomes the next spmm's output).
// flag=0: acc += B, zero A ; flag=1: acc += A, zero B
__global__ void fuse_kernel(int flag) {
    int i = blockIdx.x * blockDim.x + threadIdx.x;
    if (i >= NV) return;
    float4 s = flag ? g_A[i] : g_B[i];
    float4 a = g_acc[i];
    g_acc[i] = make_float4(a.x + s.x, a.y + s.y, a.z + s.z, a.w + s.w);
    float4 z = make_float4(0.f, 0.f, 0.f, 0.f);
    if (flag) g_B[i] = z; else g_A[i] = z;
}

// out = concat(user_out, item_out); last acc += B fused in; scale by 1/4.
// user_out[i]  = (acc + B)[i] / 4                      for node i < NUP1
// item_out[0]  = 0
// item_out[r]  = (acc + B)[NUP1 + r - 1] / 4           for r in [1, 100000]
__global__ void final_kernel(float4* __restrict__ out) {
    int i = blockIdx.x * blockDim.x + threadIdx.x;
    const int total = 2 * NUP1 * 16;
    if (i >= total) return;

    if (i < NUP1 * 16) {
        float4 a = g_acc[i];
        float4 b = g_B[i];
        out[i] = make_float4((a.x + b.x) * 0.25f, (a.y + b.y) * 0.25f,
                             (a.z + b.z) * 0.25f, (a.w + b.w) * 0.25f);
    } else {
        int j = i - NUP1 * 16;
        if (j < 16) {
            out[i] = make_float4(0.f, 0.f, 0.f, 0.f);
        } else {
            int k = NUP1 * 16 + j - 16;
            float4 a = g_acc[k];
            float4 b = g_B[k];
            out[i] = make_float4((a.x + b.x) * 0.25f, (a.y + b.y) * 0.25f,
                                 (a.z + b.z) * 0.25f, (a.w + b.w) * 0.25f);
        }
    }
}

extern "C" void kernel_launch(void* const* d_in, const int* in_sizes, int n_in,
                              void* d_out, int out_size) {
    const float4* user4 = (const float4*)d_in[0];
    const float4* item4 = (const float4*)d_in[1];
    const int*    rows  = (const int*)d_in[2];
    const int*    cols  = (const int*)d_in[3];
    const float*  vals  = (const float*)d_in[4];
    float4*       out   = (float4*)d_out;

    const int nnz = in_sizes[2];

    const int TB = 256;
    const int gridNV   = (NV + TB - 1) / TB;
    long long spmm_thr = (long long)nnz * 16;
    const int gridSp   = (int)((spmm_thr + TB - 1) / TB);
    const int gridOut  = (2 * NUP1 * 16 + TB - 1) / TB;

    init_kernel<<<gridNV, TB>>>(user4, item4);
    // layer 1: A -> B
    spmm_kernel<<<gridSp, TB>>>(rows, cols, vals, nnz, 0);
    fuse_kernel<<<gridNV, TB>>>(0);          // acc += B, zero A
    // layer 2: B -> A
    spmm_kernel<<<gridSp, TB>>>(rows, cols, vals, nnz, 1);
    fuse_kernel<<<gridNV, TB>>>(1);          // acc += A, zero B
    // layer 3: A -> B
    spmm_kernel<<<gridSp, TB>>>(rows, cols, vals, nnz, 0);
    // finalize: out = (acc + B) / 4, split into user/item halves
    final_kernel<<<gridOut, TB>>>(out);
}

// round 2
// speedup vs baseline: 1.3794x; 1.3794x over previous
#include <cuda_runtime.h>

#define NUP1   100001            // NUM_USERS + 1
#define NROWS  200001            // total nodes
#define NNZE   2000000           // fixed nnz for this problem
#define NF2    (NROWS * 32)      // float2 elements per node buffer (64 f/node)
#define SCAN_B 1024
#define NB     ((NROWS + SCAN_B - 1) / SCAN_B)   // 196 scan blocks

// ---- static device scratch (no allocations) ----
__device__ float2 g_A[NF2];
__device__ float2 g_B[NF2];
__device__ float2 g_acc[NF2];

__device__ int   g_cnt[NROWS];
__device__ int   g_incl[NROWS];
__device__ int   g_blksum[NB];
__device__ int   g_blkoff[NB];
__device__ int   g_ptr[NROWS + 1];
__device__ int   g_fill[NROWS];
__device__ int   g_ecol[NNZE];
__device__ float g_eval[NNZE];

// A = acc = concat(user_emb, item_emb[1:]); also zero g_cnt.
__global__ void init_kernel(const float2* __restrict__ user2,
                            const float2* __restrict__ item2) {
    int i = blockIdx.x * blockDim.x + threadIdx.x;
    if (i < NROWS) g_cnt[i] = 0;
    if (i >= NF2) return;
    float2 v = (i < NUP1 * 32) ? __ldg(&user2[i])
                               : __ldg(&item2[i - NUP1 * 32 + 32]);
    g_A[i]   = v;
    g_acc[i] = v;
}

__global__ void hist_kernel(const int* __restrict__ rows, int nnz) {
    int e = blockIdx.x * blockDim.x + threadIdx.x;
    if (e < nnz) atomicAdd(&g_cnt[rows[e]], 1);
}

// Block-local inclusive scan of g_cnt (1024 elems per block).
__global__ void scan1_kernel() {
    __shared__ int sh[SCAN_B];
    int t = threadIdx.x;
    int idx = blockIdx.x * SCAN_B + t;
    int val = (idx < NROWS) ? g_cnt[idx] : 0;
    sh[t] = val;
    __syncthreads();
    for (int off = 1; off < SCAN_B; off <<= 1) {
        int add = (t >= off) ? sh[t - off] : 0;
        __syncthreads();
        sh[t] += add;
        __syncthreads();
    }
    if (idx < NROWS) g_incl[idx] = sh[t];
    if (t == SCAN_B - 1) g_blksum[blockIdx.x] = sh[t];
}

// Exclusive scan of the 196 block sums (single block).
__global__ void scan2_kernel() {
    __shared__ int sh[256];
    int t = threadIdx.x;
    int val = (t < NB) ? g_blksum[t] : 0;
    sh[t] = val;
    __syncthreads();
    for (int off = 1; off < 256; off <<= 1) {
        int add = (t >= off) ? sh[t - off] : 0;
        __syncthreads();
        sh[t] += add;
        __syncthreads();
    }
    if (t < NB) g_blkoff[t] = sh[t] - val;   // exclusive
}

// row_ptr (exclusive) + fill cursors.
__global__ void scan3_kernel(int nnz) {
    int idx = blockIdx.x * blockDim.x + threadIdx.x;
    if (idx >= NROWS) return;
    int excl = g_blkoff[idx >> 10] + g_incl[idx] - g_cnt[idx];
    g_ptr[idx]  = excl;
    g_fill[idx] = excl;
    if (idx == 0) g_ptr[NROWS] = nnz;
}

// Bucket edges into CSR order.
__global__ void scatter_kernel(const int* __restrict__ rows,
                               const int* __restrict__ cols,
                               const float* __restrict__ vals, int nnz) {
    int e = blockIdx.x * blockDim.x + threadIdx.x;
    if (e >= nnz) return;
    int r = rows[e];
    int pos = atomicAdd(&g_fill[r], 1);
    g_ecol[pos] = cols[e];
    g_eval[pos] = vals[e];
}

// One warp per row. dir=0: x=A,y=B ; dir=1: x=B,y=A.
// mode=0: y = sum; acc += sum.
// mode=1: out[remap(row)] = (acc + sum) * 0.25 (final layer, fused epilogue).
__global__ void spmm_csr(int dir, int mode, float2* __restrict__ out) {
    int warp = (blockIdx.x * blockDim.x + threadIdx.x) >> 5;
    int lane = threadIdx.x & 31;
    if (warp >= NROWS) return;

    const float2* __restrict__ x = dir ? g_B : g_A;
    float2*       __restrict__ y = dir ? g_A : g_B;

    int s = g_ptr[warp];
    int e = g_ptr[warp + 1];

    float2 sum = make_float2(0.f, 0.f);
    for (int base = s; base < e; base += 32) {
        int idx = base + lane;
        int c = 0; float v = 0.f;
        if (idx < e) { c = g_ecol[idx]; v = g_eval[idx]; }
        int cnt = min(32, e - base);
        for (int j = 0; j < cnt; j++) {
            int   cj = __shfl_sync(0xffffffffu, c, j);
            float vj = __shfl_sync(0xffffffffu, v, j);
            float2 xv = __ldg(&x[(size_t)cj * 32 + lane]);
            sum.x = fmaf(vj, xv.x, sum.x);
            sum.y = fmaf(vj, xv.y, sum.y);
        }
    }

    size_t o = (size_t)warp * 32 + lane;
    if (mode == 0) {
        y[o] = sum;
        float2 a = g_acc[o];
        g_acc[o] = make_float2(a.x + sum.x, a.y + sum.y);
    } else {
        int outrow = (warp < NUP1) ? warp : warp + 1;  // item r -> slot r+1
        float2 a = g_acc[o];
        out[(size_t)outrow * 32 + lane] =
            make_float2((a.x + sum.x) * 0.25f, (a.y + sum.y) * 0.25f);
        if (warp == 0)   // item_out[0] = 0
            out[(size_t)NUP1 * 32 + lane] = make_float2(0.f, 0.f);
    }
}

extern "C" void kernel_launch(void* const* d_in, const int* in_sizes, int n_in,
                              void* d_out, int out_size) {
    const float2* user2 = (const float2*)d_in[0];
    const float2* item2 = (const float2*)d_in[1];
    const int*    rows  = (const int*)d_in[2];
    const int*    cols  = (const int*)d_in[3];
    const float*  vals  = (const float*)d_in[4];
    float2*       out   = (float2*)d_out;

    const int nnz = in_sizes[2];
    const int TB = 256;

    const int gInit  = (NF2 + TB - 1) / TB;
    const int gEdge  = (nnz + TB - 1) / TB;
    const int gRows  = (NROWS + TB - 1) / TB;
    const int gSpmm  = (NROWS * 32 + TB - 1) / TB;   // one warp per row

    init_kernel<<<gInit, TB>>>(user2, item2);
    hist_kernel<<<gEdge, TB>>>(rows, nnz);
    scan1_kernel<<<NB, SCAN_B>>>();
    scan2_kernel<<<1, 256>>>();
    scan3_kernel<<<gRows, TB>>>(nnz);
    scatter_kernel<<<gEdge, TB>>>(rows, cols, vals, nnz);

    spmm_csr<<<gSpmm, TB>>>(0, 0, nullptr);  // A -> B, acc += B
    spmm_csr<<<gSpmm, TB>>>(1, 0, nullptr);  // B -> A, acc += A
    spmm_csr<<<gSpmm, TB>>>(0, 1, out);      // A -> B(final) fused into out
}

// round 4
// speedup vs baseline: 1.8713x; 1.3566x over previous
#include <cuda_runtime.h>

#define NUP1   100001            // NUM_USERS + 1
#define NROWS  200001            // total nodes
#define NNZE   2000000
#define NF2    (NROWS * 32)      // float2 elements per node buffer
#define SCAN_B 1024
#define NB     ((NROWS + SCAN_B - 1) / SCAN_B)   // 196

// ---- static device scratch ----
__device__ float2 g_A[NF2];      // layer 0 (original embeddings)
__device__ float2 g_B[NF2];      // layer 1 output
__device__ float2 g_C[NF2];      // layer 2 output

__device__ int   g_cnt[NROWS];
__device__ int   g_incl[NROWS];
__device__ int   g_blksum[NB];
__device__ int   g_blkoff[NB];
__device__ int   g_ptr[NROWS + 1];
__device__ int   g_fill[NROWS];
__device__ int2  g_edge[NNZE];   // packed (col, val-bits)

__global__ void init_kernel(const float2* __restrict__ user2,
                            const float2* __restrict__ item2) {
    int i = blockIdx.x * blockDim.x + threadIdx.x;
    if (i < NROWS) g_cnt[i] = 0;
    if (i >= NF2) return;
    g_A[i] = (i < NUP1 * 32) ? __ldg(&user2[i])
                             : __ldg(&item2[i - NUP1 * 32 + 32]);
}

__global__ void hist_kernel(const int* __restrict__ rows, int nnz) {
    int e = blockIdx.x * blockDim.x + threadIdx.x;
    if (e < nnz) atomicAdd(&g_cnt[rows[e]], 1);
}

__global__ void scan1_kernel() {
    __shared__ int sh[SCAN_B];
    int t = threadIdx.x;
    int idx = blockIdx.x * SCAN_B + t;
    int val = (idx < NROWS) ? g_cnt[idx] : 0;
    sh[t] = val;
    __syncthreads();
    for (int off = 1; off < SCAN_B; off <<= 1) {
        int add = (t >= off) ? sh[t - off] : 0;
        __syncthreads();
        sh[t] += add;
        __syncthreads();
    }
    if (idx < NROWS) g_incl[idx] = sh[t];
    if (t == SCAN_B - 1) g_blksum[blockIdx.x] = sh[t];
}

__global__ void scan2_kernel() {
    __shared__ int sh[256];
    int t = threadIdx.x;
    int val = (t < NB) ? g_blksum[t] : 0;
    sh[t] = val;
    __syncthreads();
    for (int off = 1; off < 256; off <<= 1) {
        int add = (t >= off) ? sh[t - off] : 0;
        __syncthreads();
        sh[t] += add;
        __syncthreads();
    }
    if (t < NB) g_blkoff[t] = sh[t] - val;
}

__global__ void scan3_kernel(int nnz) {
    int idx = blockIdx.x * blockDim.x + threadIdx.x;
    if (idx >= NROWS) return;
    int excl = g_blkoff[idx >> 10] + g_incl[idx] - g_cnt[idx];
    g_ptr[idx]  = excl;
    g_fill[idx] = excl;
    if (idx == 0) g_ptr[NROWS] = nnz;
}

__global__ void scatter_kernel(const int* __restrict__ rows,
                               const int* __restrict__ cols,
                               const float* __restrict__ vals, int nnz) {
    int e = blockIdx.x * blockDim.x + threadIdx.x;
    if (e >= nnz) return;
    int r = rows[e];
    int pos = atomicAdd(&g_fill[r], 1);
    g_edge[pos] = make_int2(cols[e], __float_as_int(vals[e]));
}

// One warp per row; padded 4-way unrolled gather for MLP.
__device__ __forceinline__ float2 row_spmv(const float2* __restrict__ x,
                                           int s, int e, int lane) {
    float2 sum = make_float2(0.f, 0.f);
    for (int base = s; base < e; base += 32) {
        int idx = base + lane;
        int2 ev = (idx < e) ? g_edge[idx] : make_int2(0, 0);
        int   c = ev.x;
        float v = __int_as_float(ev.y);
        int cnt4 = (min(32, e - base) + 3) & ~3;
        for (int j = 0; j < cnt4; j += 4) {
            int   c0 = __shfl_sync(0xffffffffu, c, j + 0);
            int   c1 = __shfl_sync(0xffffffffu, c, j + 1);
            int   c2 = __shfl_sync(0xffffffffu, c, j + 2);
            int   c3 = __shfl_sync(0xffffffffu, c, j + 3);
            float v0 = __shfl_sync(0xffffffffu, v, j + 0);
            float v1 = __shfl_sync(0xffffffffu, v, j + 1);
            float v2 = __shfl_sync(0xffffffffu, v, j + 2);
            float v3 = __shfl_sync(0xffffffffu, v, j + 3);
            float2 x0 = __ldg(&x[c0 * 32 + lane]);
            float2 x1 = __ldg(&x[c1 * 32 + lane]);
            float2 x2 = __ldg(&x[c2 * 32 + lane]);
            float2 x3 = __ldg(&x[c3 * 32 + lane]);
            sum.x = fmaf(v0, x0.x, sum.x);
            sum.y = fmaf(v0, x0.y, sum.y);
            sum.x = fmaf(v1, x1.x, sum.x);
            sum.y = fmaf(v1, x1.y, sum.y);
            sum.x = fmaf(v2, x2.x, sum.x);
            sum.y = fmaf(v2, x2.y, sum.y);
            sum.x = fmaf(v3, x3.x, sum.x);
            sum.y = fmaf(v3, x3.y, sum.y);
        }
    }
    return sum;
}

// layer 1/2: buffer selection done IN DEVICE CODE (no host-side symbol addr).
__global__ void spmm_mid(int layer) {
    int warp = (blockIdx.x * blockDim.x + threadIdx.x) >> 5;
    int lane = threadIdx.x & 31;
    if (warp >= NROWS) return;
    const float2* __restrict__ x = (layer == 0) ? g_A : g_B;
    float2*       __restrict__ y = (layer == 0) ? g_B : g_C;
    float2 sum = row_spmv(x, g_ptr[warp], g_ptr[warp + 1], lane);
    y[warp * 32 + lane] = sum;
}

// final layer: out[remap(row)] = (A + B + C + spmv(C)) * 0.25
__global__ void spmm_final(float2* __restrict__ out) {
    int warp = (blockIdx.x * blockDim.x + threadIdx.x) >> 5;
    int lane = threadIdx.x & 31;
    if (warp >= NROWS) return;
    float2 sum = row_spmv(g_C, g_ptr[warp], g_ptr[warp + 1], lane);
    int o = warp * 32 + lane;
    float2 a = g_A[o], b = g_B[o], c = g_C[o];
    int outrow = (warp < NUP1) ? warp : warp + 1;
    out[(size_t)outrow * 32 + lane] =
        make_float2((a.x + b.x + c.x + sum.x) * 0.25f,
                    (a.y + b.y + c.y + sum.y) * 0.25f);
    if (warp == 0)
        out[(size_t)NUP1 * 32 + lane] = make_float2(0.f, 0.f);
}

extern "C" void kernel_launch(void* const* d_in, const int* in_sizes, int n_in,
                              void* d_out, int out_size) {
    const float2* user2 = (const float2*)d_in[0];
    const float2* item2 = (const float2*)d_in[1];
    const int*    rows  = (const int*)d_in[2];
    const int*    cols  = (const int*)d_in[3];
    const float*  vals  = (const float*)d_in[4];
    float2*       out   = (float2*)d_out;

    const int nnz = in_sizes[2];
    const int TB = 256;

    const int gInit = (NF2 + TB - 1) / TB;
    const int gEdge = (nnz + TB - 1) / TB;
    const int gRows = (NROWS + TB - 1) / TB;
    const int gSpmm = (NROWS * 32 + TB - 1) / TB;

    init_kernel<<<gInit, TB>>>(user2, item2);
    hist_kernel<<<gEdge, TB>>>(rows, nnz);
    scan1_kernel<<<NB, SCAN_B>>>();
    scan2_kernel<<<1, 256>>>();
    scan3_kernel<<<gRows, TB>>>(nnz);
    scatter_kernel<<<gEdge, TB>>>(rows, cols, vals, nnz);

    spmm_mid<<<gSpmm, TB>>>(0);   // A -> B
    spmm_mid<<<gSpmm, TB>>>(1);   // B -> C
    spmm_final<<<gSpmm, TB>>>(out);
}

// round 5
// speedup vs baseline: 2.0560x; 1.0987x over previous
#include <cuda_runtime.h>
#include <cuda_fp16.h>

#define NUP1   100001            // NUM_USERS + 1
#define NROWS  200001            // total nodes
#define NNZE   2000000
#define NF2    (NROWS * 32)      // 32 x (float2|half2) per node = 64 scalars
#define SCAN_B 1024
#define NB     ((NROWS + SCAN_B - 1) / SCAN_B)   // 196

// ---- static device scratch ----
__device__ float2 g_A  [NF2];    // layer 0, fp32 (exact dominant term)
__device__ __half2 g_A16[NF2];   // fp16 mirror of layer 0 (gather source)
__device__ __half2 g_B16[NF2];   // layer 1 output (fp16)
__device__ __half2 g_C16[NF2];   // layer 2 output (fp16)

__device__ int   g_cnt[NROWS];
__device__ int   g_incl[NROWS];
__device__ int   g_blksum[NB];
__device__ int   g_blkoff[NB];
__device__ int   g_ptr[NROWS + 1];
__device__ int   g_fill[NROWS];
__device__ int2  g_edge[NNZE];   // packed (col, fp32 val bits)

__global__ void init_kernel(const float2* __restrict__ user2,
                            const float2* __restrict__ item2) {
    int i = blockIdx.x * blockDim.x + threadIdx.x;
    if (i < NROWS) g_cnt[i] = 0;
    if (i >= NF2) return;
    float2 v = (i < NUP1 * 32) ? __ldg(&user2[i])
                               : __ldg(&item2[i - NUP1 * 32 + 32]);
    g_A[i]   = v;
    g_A16[i] = __float22half2_rn(v);
}

__global__ void hist_kernel(const int* __restrict__ rows, int nnz) {
    int e = blockIdx.x * blockDim.x + threadIdx.x;
    if (e < nnz) atomicAdd(&g_cnt[rows[e]], 1);
}

__global__ void scan1_kernel() {
    __shared__ int sh[SCAN_B];
    int t = threadIdx.x;
    int idx = blockIdx.x * SCAN_B + t;
    int val = (idx < NROWS) ? g_cnt[idx] : 0;
    sh[t] = val;
    __syncthreads();
    for (int off = 1; off < SCAN_B; off <<= 1) {
        int add = (t >= off) ? sh[t - off] : 0;
        __syncthreads();
        sh[t] += add;
        __syncthreads();
    }
    if (idx < NROWS) g_incl[idx] = sh[t];
    if (t == SCAN_B - 1) g_blksum[blockIdx.x] = sh[t];
}

__global__ void scan2_kernel() {
    __shared__ int sh[256];
    int t = threadIdx.x;
    int val = (t < NB) ? g_blksum[t] : 0;
    sh[t] = val;
    __syncthreads();
    for (int off = 1; off < 256; off <<= 1) {
        int add = (t >= off) ? sh[t - off] : 0;
        __syncthreads();
        sh[t] += add;
        __syncthreads();
    }
    if (t < NB) g_blkoff[t] = sh[t] - val;
}

__global__ void scan3_kernel(int nnz) {
    int idx = blockIdx.x * blockDim.x + threadIdx.x;
    if (idx >= NROWS) return;
    int excl = g_blkoff[idx >> 10] + g_incl[idx] - g_cnt[idx];
    g_ptr[idx]  = excl;
    g_fill[idx] = excl;
    if (idx == 0) g_ptr[NROWS] = nnz;
}

__global__ void scatter_kernel(const int* __restrict__ rows,
                               const int* __restrict__ cols,
                               const float* __restrict__ vals, int nnz) {
    int e = blockIdx.x * blockDim.x + threadIdx.x;
    if (e >= nnz) return;
    int r = rows[e];
    int pos = atomicAdd(&g_fill[r], 1);
    g_edge[pos] = make_int2(cols[e], __float_as_int(vals[e]));
}

// One warp per row; padded 4-way unrolled half2 gather, fp32 accumulate.
__device__ __forceinline__ float2 row_spmv16(const __half2* __restrict__ x,
                                             int s, int e, int lane) {
    float2 sum = make_float2(0.f, 0.f);
    for (int base = s; base < e; base += 32) {
        int idx = base + lane;
        int2 ev = (idx < e) ? g_edge[idx] : make_int2(0, 0);
        int   c = ev.x;
        float v = __int_as_float(ev.y);
        int cnt4 = (min(32, e - base) + 3) & ~3;
        for (int j = 0; j < cnt4; j += 4) {
            int   c0 = __shfl_sync(0xffffffffu, c, j + 0);
            int   c1 = __shfl_sync(0xffffffffu, c, j + 1);
            int   c2 = __shfl_sync(0xffffffffu, c, j + 2);
            int   c3 = __shfl_sync(0xffffffffu, c, j + 3);
            float v0 = __shfl_sync(0xffffffffu, v, j + 0);
            float v1 = __shfl_sync(0xffffffffu, v, j + 1);
            float v2 = __shfl_sync(0xffffffffu, v, j + 2);
            float v3 = __shfl_sync(0xffffffffu, v, j + 3);
            __half2 h0 = __ldg(&x[c0 * 32 + lane]);
            __half2 h1 = __ldg(&x[c1 * 32 + lane]);
            __half2 h2 = __ldg(&x[c2 * 32 + lane]);
            __half2 h3 = __ldg(&x[c3 * 32 + lane]);
            float2 x0 = __half22float2(h0);
            float2 x1 = __half22float2(h1);
            float2 x2 = __half22float2(h2);
            float2 x3 = __half22float2(h3);
            sum.x = fmaf(v0, x0.x, sum.x);
            sum.y = fmaf(v0, x0.y, sum.y);
            sum.x = fmaf(v1, x1.x, sum.x);
            sum.y = fmaf(v1, x1.y, sum.y);
            sum.x = fmaf(v2, x2.x, sum.x);
            sum.y = fmaf(v2, x2.y, sum.y);
            sum.x = fmaf(v3, x3.x, sum.x);
            sum.y = fmaf(v3, x3.y, sum.y);
        }
    }
    return sum;
}

// layer 1/2: buffer selection in device code.
__global__ void spmm_mid(int layer) {
    int warp = (blockIdx.x * blockDim.x + threadIdx.x) >> 5;
    int lane = threadIdx.x & 31;
    if (warp >= NROWS) return;
    const __half2* __restrict__ x = (layer == 0) ? g_A16 : g_B16;
    __half2*       __restrict__ y = (layer == 0) ? g_B16 : g_C16;
    float2 sum = row_spmv16(x, g_ptr[warp], g_ptr[warp + 1], lane);
    y[warp * 32 + lane] = __float22half2_rn(sum);
}

// final layer: out[remap(row)] = (A + B + C + spmv(C)) * 0.25
__global__ void spmm_final(float2* __restrict__ out) {
    int warp = (blockIdx.x * blockDim.x + threadIdx.x) >> 5;
    int lane = threadIdx.x & 31;
    if (warp >= NROWS) return;
    float2 sum = row_spmv16(g_C16, g_ptr[warp], g_ptr[warp + 1], lane);
    int o = warp * 32 + lane;
    float2 a = g_A[o];
    float2 b = __half22float2(g_B16[o]);
    float2 c = __half22float2(g_C16[o]);
    int outrow = (warp < NUP1) ? warp : warp + 1;
    out[(size_t)outrow * 32 + lane] =
        make_float2((a.x + b.x + c.x + sum.x) * 0.25f,
                    (a.y + b.y + c.y + sum.y) * 0.25f);
    if (warp == 0)
        out[(size_t)NUP1 * 32 + lane] = make_float2(0.f, 0.f);
}

extern "C" void kernel_launch(void* const* d_in, const int* in_sizes, int n_in,
                              void* d_out, int out_size) {
    const float2* user2 = (const float2*)d_in[0];
    const float2* item2 = (const float2*)d_in[1];
    const int*    rows  = (const int*)d_in[2];
    const int*    cols  = (const int*)d_in[3];
    const float*  vals  = (const float*)d_in[4];
    float2*       out   = (float2*)d_out;

    const int nnz = in_sizes[2];
    const int TB = 256;

    const int gInit = (NF2 + TB - 1) / TB;
    const int gEdge = (nnz + TB - 1) / TB;
    const int gRows = (NROWS + TB - 1) / TB;
    const int gSpmm = (NROWS * 32 + TB - 1) / TB;

    init_kernel<<<gInit, TB>>>(user2, item2);
    hist_kernel<<<gEdge, TB>>>(rows, nnz);
    scan1_kernel<<<NB, SCAN_B>>>();
    scan2_kernel<<<1, 256>>>();
    scan3_kernel<<<gRows, TB>>>(nnz);
    scatter_kernel<<<gEdge, TB>>>(rows, cols, vals, nnz);

    spmm_mid<<<gSpmm, TB>>>(0);   // A16 -> B16
    spmm_mid<<<gSpmm, TB>>>(1);   // B16 -> C16
    spmm_final<<<gSpmm, TB>>>(out);
}